// round 1
// baseline (speedup 1.0000x reference)
#include <cuda_runtime.h>

// Shapes (fixed by the problem)
//   x_q: (2,4096,2048) f32   x_k: (2,4096,2048) f32
//   Wq: (2048,256)  Ww: (2048,4)  Wk: (2048,64)
//   out: (2,4096,4096) f32
// out[b,q,k] = sum_h w_I[b,q,h] * relu( dot_d( q_I[b,q,h,d], k_I[b,k,d] ) )

#define BQ 2
#define TQDIM 4096
#define TKDIM 4096
#define DMODEL 2048
#define NHEADS 4
#define IDXDIM 64

__device__ float g_qI[8192 * 256];  // (B*Tq, H*64)
__device__ float g_kI[8192 * 64];   // (B*Tk, 64)
__device__ float g_wI[8192 * 4];    // (B*Tq, H)

// ---------------------------------------------------------------------------
// Generic projection SGEMM: C[M,N] = A[M,K] @ W[K,N]
// tile 128(M) x 64(N), KT=32, 256 threads, 8x4 per thread.
// ---------------------------------------------------------------------------
__global__ __launch_bounds__(256) void proj_kernel(
    const float* __restrict__ A, const float* __restrict__ W,
    float* __restrict__ C, int N, int K) {
  __shared__ float As[32 * 129];  // [kk][m], pad 129 -> 2-way max on transpose store
  __shared__ float Ws[32 * 65];   // [kk][n], pad 65

  const int row0 = blockIdx.y * 128;
  const int col0 = blockIdx.x * 64;
  const int tid = threadIdx.x;
  const int ty = tid >> 4;        // 0..15
  const int tx = tid & 15;        // 0..15
  const int mb = ty * 8;
  const int nb = tx * 4;

  float acc[8][4] = {};

  for (int k0 = 0; k0 < K; k0 += 32) {
    __syncthreads();
    // A tile: 128 rows x 32 k -> transposed As[kk][m]
#pragma unroll
    for (int l = 0; l < 4; l++) {
      int idx = tid + l * 256;
      int r = idx >> 3;           // 0..127
      int c4 = idx & 7;           // 8 float4 per row (32 floats)
      float4 v = *(const float4*)&A[(size_t)(row0 + r) * K + k0 + c4 * 4];
      As[(c4 * 4 + 0) * 129 + r] = v.x;
      As[(c4 * 4 + 1) * 129 + r] = v.y;
      As[(c4 * 4 + 2) * 129 + r] = v.z;
      As[(c4 * 4 + 3) * 129 + r] = v.w;
    }
    // W tile: 32 k rows x 64 cols -> Ws[kk][n]
#pragma unroll
    for (int l = 0; l < 2; l++) {
      int idx = tid + l * 256;
      int r = idx >> 4;           // 0..31
      int c4 = idx & 15;          // 16 float4 per row (64 floats)
      float4 v = *(const float4*)&W[(size_t)(k0 + r) * N + col0 + c4 * 4];
      Ws[r * 65 + c4 * 4 + 0] = v.x;
      Ws[r * 65 + c4 * 4 + 1] = v.y;
      Ws[r * 65 + c4 * 4 + 2] = v.z;
      Ws[r * 65 + c4 * 4 + 3] = v.w;
    }
    __syncthreads();
#pragma unroll 8
    for (int kk = 0; kk < 32; kk++) {
      float a[8], w[4];
#pragma unroll
      for (int i = 0; i < 8; i++) a[i] = As[kk * 129 + mb + i];
#pragma unroll
      for (int j = 0; j < 4; j++) w[j] = Ws[kk * 65 + nb + j];
#pragma unroll
      for (int i = 0; i < 8; i++)
#pragma unroll
        for (int j = 0; j < 4; j++) acc[i][j] = fmaf(a[i], w[j], acc[i][j]);
    }
  }

#pragma unroll
  for (int i = 0; i < 8; i++) {
    float4 v = make_float4(acc[i][0], acc[i][1], acc[i][2], acc[i][3]);
    *(float4*)&C[(size_t)(row0 + mb + i) * N + col0 + nb] = v;
  }
}

// ---------------------------------------------------------------------------
// w_I = x_q @ Ww  (N=4): one warp per row, warp reduction.
// ---------------------------------------------------------------------------
__global__ __launch_bounds__(128) void wproj_kernel(
    const float* __restrict__ x, const float* __restrict__ Ww,
    float* __restrict__ wI) {
  int row = blockIdx.x * 4 + (threadIdx.x >> 5);
  int lane = threadIdx.x & 31;
  const float* xr = x + (size_t)row * DMODEL;
  float a0 = 0.f, a1 = 0.f, a2 = 0.f, a3 = 0.f;
  for (int d = lane; d < DMODEL; d += 32) {
    float xv = xr[d];
    float4 w = *(const float4*)&Ww[d * 4];
    a0 = fmaf(xv, w.x, a0);
    a1 = fmaf(xv, w.y, a1);
    a2 = fmaf(xv, w.z, a2);
    a3 = fmaf(xv, w.w, a3);
  }
#pragma unroll
  for (int off = 16; off; off >>= 1) {
    a0 += __shfl_down_sync(0xffffffffu, a0, off);
    a1 += __shfl_down_sync(0xffffffffu, a1, off);
    a2 += __shfl_down_sync(0xffffffffu, a2, off);
    a3 += __shfl_down_sync(0xffffffffu, a3, off);
  }
  if (lane == 0) *(float4*)&wI[(size_t)row * 4] = make_float4(a0, a1, a2, a3);
}

// ---------------------------------------------------------------------------
// Main scores kernel: block = 128q x 64k, loop over 4 heads.
// smem: q_s[64d][128q] stride 129 (reloaded per head),
//       k_s[64d][64k]  stride 65  (loaded once),
//       w_s[128q][4h]
// per thread: 8q x 4k micro-tile; per-head dot -> relu -> weighted accumulate.
// ---------------------------------------------------------------------------
#define MAIN_SMEM_FLOATS (64 * 129 + 64 * 65 + 128 * 4)
#define MAIN_SMEM_BYTES (MAIN_SMEM_FLOATS * 4)

__global__ __launch_bounds__(256) void main_kernel(
    const float* __restrict__ qI, const float* __restrict__ kI,
    const float* __restrict__ wI, float* __restrict__ out) {
  extern __shared__ float smem[];
  float* q_s = smem;                 // 64*129
  float* k_s = smem + 64 * 129;      // 64*65
  float* w_s = k_s + 64 * 65;        // 128*4

  const int b = blockIdx.z;
  const int q0 = blockIdx.y * 128;
  const int k0 = blockIdx.x * 64;
  const int tid = threadIdx.x;
  const int ty = tid >> 4;           // 0..15
  const int tx = tid & 15;           // 0..15
  const int qb = ty * 8;
  const int kb = tx * 4;

  // k tile: 64 rows x 64 d -> transposed k_s[d][k]
  const float* kbase = kI + ((size_t)b * TKDIM + k0) * IDXDIM;
#pragma unroll
  for (int l = 0; l < 4; l++) {
    int idx = tid + l * 256;
    int r = idx >> 4;                // 0..63 (k row)
    int c4 = idx & 15;               // 16 float4 per row
    float4 v = *(const float4*)&kbase[r * IDXDIM + c4 * 4];
    k_s[(c4 * 4 + 0) * 65 + r] = v.x;
    k_s[(c4 * 4 + 1) * 65 + r] = v.y;
    k_s[(c4 * 4 + 2) * 65 + r] = v.z;
    k_s[(c4 * 4 + 3) * 65 + r] = v.w;
  }
  if (tid < 128) {
    float4 v = *(const float4*)&wI[((size_t)b * TQDIM + q0 + tid) * 4];
    *(float4*)&w_s[tid * 4] = v;
  }

  float acc[8][4] = {};
  const float* qbase = qI + ((size_t)b * TQDIM + q0) * 256;

  for (int h = 0; h < NHEADS; h++) {
    __syncthreads();  // previous-head compute done before q_s overwrite
    // q tile (this head): 128 rows x 64 d -> transposed q_s[d][q]
#pragma unroll
    for (int l = 0; l < 8; l++) {
      int idx = tid + l * 256;
      int r = idx >> 4;              // 0..127 (q row)
      int c4 = idx & 15;
      float4 v = *(const float4*)&qbase[r * 256 + h * 64 + c4 * 4];
      q_s[(c4 * 4 + 0) * 129 + r] = v.x;
      q_s[(c4 * 4 + 1) * 129 + r] = v.y;
      q_s[(c4 * 4 + 2) * 129 + r] = v.z;
      q_s[(c4 * 4 + 3) * 129 + r] = v.w;
    }
    __syncthreads();

    float dot[8][4] = {};
#pragma unroll 16
    for (int d = 0; d < 64; d++) {
      float qa[8], ka[4];
#pragma unroll
      for (int i = 0; i < 8; i++) qa[i] = q_s[d * 129 + qb + i];
#pragma unroll
      for (int j = 0; j < 4; j++) ka[j] = k_s[d * 65 + kb + j];
#pragma unroll
      for (int i = 0; i < 8; i++)
#pragma unroll
        for (int j = 0; j < 4; j++) dot[i][j] = fmaf(qa[i], ka[j], dot[i][j]);
    }
#pragma unroll
    for (int i = 0; i < 8; i++) {
      float w = w_s[(qb + i) * 4 + h];
#pragma unroll
      for (int j = 0; j < 4; j++)
        acc[i][j] = fmaf(w, fmaxf(dot[i][j], 0.f), acc[i][j]);
    }
  }

  float* obase = out + ((size_t)b * TQDIM + q0) * (size_t)TKDIM + k0;
#pragma unroll
  for (int i = 0; i < 8; i++) {
    float4 v = make_float4(acc[i][0], acc[i][1], acc[i][2], acc[i][3]);
    *(float4*)&obase[(size_t)(qb + i) * TKDIM + kb] = v;
  }
}

// ---------------------------------------------------------------------------
extern "C" void kernel_launch(void* const* d_in, const int* in_sizes, int n_in,
                              void* d_out, int out_size) {
  const float* x_q = (const float*)d_in[0];
  const float* x_k = (const float*)d_in[1];
  const float* Wq = (const float*)d_in[2];
  const float* Ww = (const float*)d_in[3];
  const float* Wk = (const float*)d_in[4];
  float* out = (float*)d_out;

  float *qI, *kI, *wI;
  cudaGetSymbolAddress((void**)&qI, g_qI);
  cudaGetSymbolAddress((void**)&kI, g_kI);
  cudaGetSymbolAddress((void**)&wI, g_wI);

  dim3 blk(256);
  // q_I = x_q @ Wq : M=8192, N=256, K=2048
  proj_kernel<<<dim3(256 / 64, 8192 / 128), blk>>>(x_q, Wq, qI, 256, DMODEL);
  // k_I = x_k @ Wk : M=8192, N=64, K=2048
  proj_kernel<<<dim3(1, 8192 / 128), blk>>>(x_k, Wk, kI, 64, DMODEL);
  // w_I = x_q @ Ww : M=8192, N=4
  wproj_kernel<<<2048, 128>>>(x_q, Ww, wI);

  cudaFuncSetAttribute(main_kernel, cudaFuncAttributeMaxDynamicSharedMemorySize,
                       MAIN_SMEM_BYTES);
  main_kernel<<<dim3(TKDIM / 64, TQDIM / 128, BQ), blk, MAIN_SMEM_BYTES>>>(
      qI, kI, wI, out);
}

// round 3
// speedup vs baseline: 1.8881x; 1.8881x over previous
#include <cuda_runtime.h>
#include <cuda_bf16.h>
#include <cstdint>

// Shapes (fixed)
#define TQDIM 4096
#define TKDIM 4096
#define DMODEL 2048
#define NHEADS 4
#define ROWS 8192  // B*T

#define SP 72   // smem row stride in bf16 halves (conflict-free frag LDS)
#define SPW 36  // stride in 32-bit words

__device__ float g_qI[ROWS * 256];
__device__ float g_kI[ROWS * 64];
__device__ float g_wI[ROWS * 4];

// ---------------------------------------------------------------------------
// helpers
// ---------------------------------------------------------------------------
__device__ __forceinline__ void split1(float v, __nv_bfloat16& h,
                                       __nv_bfloat16& l) {
  h = __float2bfloat16(v);
  l = __float2bfloat16(v - __bfloat162float(h));
}
__device__ __forceinline__ uint32_t pack2(__nv_bfloat16 a, __nv_bfloat16 b) {
  return (uint32_t)__bfloat16_as_ushort(a) |
         ((uint32_t)__bfloat16_as_ushort(b) << 16);
}
// float4 -> hi uint2 / lo uint2 (4 halves each)
__device__ __forceinline__ void split_f4(float4 v, uint2& hi, uint2& lo) {
  __nv_bfloat16 h0, l0, h1, l1, h2, l2, h3, l3;
  split1(v.x, h0, l0); split1(v.y, h1, l1);
  split1(v.z, h2, l2); split1(v.w, h3, l3);
  hi.x = pack2(h0, h1); hi.y = pack2(h2, h3);
  lo.x = pack2(l0, l1); lo.y = pack2(l2, l3);
}

// m16n8k16 row.col f32.bf16.bf16.f32
__device__ __forceinline__ void mma_bf16(float* c, const uint32_t* a,
                                         uint32_t b0, uint32_t b1) {
  asm volatile(
      "mma.sync.aligned.m16n8k16.row.col.f32.bf16.bf16.f32 "
      "{%0,%1,%2,%3}, {%4,%5,%6,%7}, {%8,%9}, {%0,%1,%2,%3};\n"
      : "+f"(c[0]), "+f"(c[1]), "+f"(c[2]), "+f"(c[3])
      : "r"(a[0]), "r"(a[1]), "r"(a[2]), "r"(a[3]), "r"(b0), "r"(b1));
}

// ---------------------------------------------------------------------------
// Projection GEMM body (bf16x3 via mma.sync): C[M,Nld] = A[M,K] @ W[K,Nld]
// CTA tile: 128 x NT. NT=128 -> warps 4x2 (MF=2), NT=64 -> warps 8x1 (MF=1).
// ---------------------------------------------------------------------------
template <int NT, int MF>
__device__ __forceinline__ void proj_body(const float* __restrict__ A,
                                          const float* __restrict__ W,
                                          float* __restrict__ C, int Nld,
                                          int m0, int n0) {
  extern __shared__ __align__(16) char smem[];
  __nv_bfloat16* Ah = (__nv_bfloat16*)smem;            // 128*SP
  __nv_bfloat16* Al = Ah + 128 * SP;
  __nv_bfloat16* Bh = Al + 128 * SP;                   // NT*SP
  __nv_bfloat16* Bl = Bh + NT * SP;
  const uint32_t* AhW = (const uint32_t*)Ah;
  const uint32_t* AlW = (const uint32_t*)Al;
  const uint32_t* BhW = (const uint32_t*)Bh;
  const uint32_t* BlW = (const uint32_t*)Bl;

  const int tid = threadIdx.x;
  const int wid = tid >> 5, lane = tid & 31;
  const int g = lane >> 2, q4 = lane & 3;
  const int mw = (MF == 2) ? (wid >> 1) * 32 : wid * 16;
  const int nw = (MF == 2) ? (wid & 1) * 64 : 0;

  float dot[MF][8][4] = {};

  for (int kc = 0; kc < DMODEL / 64; kc++) {
    __syncthreads();
    // A chunk: 128 rows x 64 cols fp32 -> split hi/lo
#pragma unroll
    for (int l = 0; l < 8; l++) {
      int idx = tid + l * 256;
      int m = idx >> 4, c4 = idx & 15;
      float4 v = *(const float4*)(A + (size_t)(m0 + m) * DMODEL + kc * 64 +
                                  c4 * 4);
      uint2 hi, lo;
      split_f4(v, hi, lo);
      ((uint2*)Ah)[m * 18 + c4] = hi;
      ((uint2*)Al)[m * 18 + c4] = lo;
    }
    // W chunk transpose: Bh[n][kk] = W[kc*64+kk][n0+n]
#pragma unroll
    for (int l = 0; l < NT * 64 / 256; l++) {
      int idx = tid + l * 256;
      int n = idx & (NT - 1), kk = idx / NT;
      float w = W[(size_t)(kc * 64 + kk) * Nld + n0 + n];
      __nv_bfloat16 h, lo;
      split1(w, h, lo);
      Bh[n * SP + kk] = h;
      Bl[n * SP + kk] = lo;
    }
    __syncthreads();

#pragma unroll
    for (int ks = 0; ks < 4; ks++) {
      uint32_t ah[MF][4], al[MF][4];
#pragma unroll
      for (int mf = 0; mf < MF; mf++) {
        int r0 = mw + mf * 16 + g, r1 = r0 + 8;
        int w0 = ks * 8 + q4;
        ah[mf][0] = AhW[r0 * SPW + w0];
        ah[mf][1] = AhW[r1 * SPW + w0];
        ah[mf][2] = AhW[r0 * SPW + w0 + 4];
        ah[mf][3] = AhW[r1 * SPW + w0 + 4];
        al[mf][0] = AlW[r0 * SPW + w0];
        al[mf][1] = AlW[r1 * SPW + w0];
        al[mf][2] = AlW[r0 * SPW + w0 + 4];
        al[mf][3] = AlW[r1 * SPW + w0 + 4];
      }
#pragma unroll
      for (int nf = 0; nf < 8; nf++) {
        int n = nw + nf * 8 + g;
        int wb = n * SPW + ks * 8 + q4;
        uint32_t bh0 = BhW[wb], bh1 = BhW[wb + 4];
        uint32_t bl0 = BlW[wb], bl1 = BlW[wb + 4];
#pragma unroll
        for (int mf = 0; mf < MF; mf++) {
          mma_bf16(dot[mf][nf], ah[mf], bh0, bh1);
          mma_bf16(dot[mf][nf], ah[mf], bl0, bl1);
          mma_bf16(dot[mf][nf], al[mf], bh0, bh1);
        }
      }
    }
  }
  // epilogue: fp32 out
#pragma unroll
  for (int mf = 0; mf < MF; mf++) {
    int r0 = m0 + mw + mf * 16 + g;
#pragma unroll
    for (int nf = 0; nf < 8; nf++) {
      int col = n0 + nw + nf * 8 + q4 * 2;
      *(float2*)&C[(size_t)r0 * Nld + col] =
          make_float2(dot[mf][nf][0], dot[mf][nf][1]);
      *(float2*)&C[(size_t)(r0 + 8) * Nld + col] =
          make_float2(dot[mf][nf][2], dot[mf][nf][3]);
    }
  }
}

#define PROJ_SMEM ((128 * SP * 2 + 128 * SP * 2) * 2)  // 147456? -> computed below

__global__ __launch_bounds__(256, 1) void proj_kernel(
    const float* __restrict__ xq, const float* __restrict__ xk,
    const float* __restrict__ Wq, const float* __restrict__ Wk,
    float* __restrict__ qI, float* __restrict__ kI) {
  int bx = blockIdx.x;
  if (bx < 128) {
    proj_body<128, 2>(xq, Wq, qI, 256, (bx >> 1) * 128, (bx & 1) * 128);
  } else {
    proj_body<64, 1>(xk, Wk, kI, 64, (bx - 128) * 128, 0);
  }
}

// ---------------------------------------------------------------------------
// w_I = x_q @ Ww (N=4): one warp per row.
// ---------------------------------------------------------------------------
__global__ __launch_bounds__(128) void wproj_kernel(
    const float* __restrict__ x, const float* __restrict__ Ww,
    float* __restrict__ wI) {
  int row = blockIdx.x * 4 + (threadIdx.x >> 5);
  int lane = threadIdx.x & 31;
  const float* xr = x + (size_t)row * DMODEL;
  float a0 = 0.f, a1 = 0.f, a2 = 0.f, a3 = 0.f;
  for (int d = lane; d < DMODEL; d += 32) {
    float xv = xr[d];
    float4 w = *(const float4*)&Ww[d * 4];
    a0 = fmaf(xv, w.x, a0);
    a1 = fmaf(xv, w.y, a1);
    a2 = fmaf(xv, w.z, a2);
    a3 = fmaf(xv, w.w, a3);
  }
#pragma unroll
  for (int off = 16; off; off >>= 1) {
    a0 += __shfl_down_sync(0xffffffffu, a0, off);
    a1 += __shfl_down_sync(0xffffffffu, a1, off);
    a2 += __shfl_down_sync(0xffffffffu, a2, off);
    a3 += __shfl_down_sync(0xffffffffu, a3, off);
  }
  if (lane == 0) *(float4*)&wI[(size_t)row * 4] = make_float4(a0, a1, a2, a3);
}

// ---------------------------------------------------------------------------
// Main kernel: 128q x 128k tile, 8 warps (4x2), warp tile 32x64.
// Per head: dot (bf16x3 HMMA) -> relu -> w-weighted accumulate.
// Both q_I and k_I are [row][64] K-major => both load straight in, no transpose.
// ---------------------------------------------------------------------------
#define MAIN_SMEM (4 * 128 * SP * 2 + 128 * 4 * 4)

__global__ __launch_bounds__(256, 1) void main_mma_kernel(
    const float* __restrict__ qI, const float* __restrict__ kI,
    const float* __restrict__ wI, float* __restrict__ out) {
  extern __shared__ __align__(16) char smem[];
  __nv_bfloat16* Ah = (__nv_bfloat16*)smem;   // q tile hi (per head)
  __nv_bfloat16* Al = Ah + 128 * SP;
  __nv_bfloat16* Bh = Al + 128 * SP;          // k tile hi (all heads)
  __nv_bfloat16* Bl = Bh + 128 * SP;
  float* ws = (float*)(Bl + 128 * SP);        // 128 x 4
  const uint32_t* AhW = (const uint32_t*)Ah;
  const uint32_t* AlW = (const uint32_t*)Al;
  const uint32_t* BhW = (const uint32_t*)Bh;
  const uint32_t* BlW = (const uint32_t*)Bl;

  const int tid = threadIdx.x;
  const int wid = tid >> 5, lane = tid & 31;
  const int g = lane >> 2, q4 = lane & 3;
  const int mw = (wid >> 1) * 32, nw = (wid & 1) * 64;
  const int b = blockIdx.z, q0 = blockIdx.y * 128, k0 = blockIdx.x * 128;

  // k tile: 128 rows x 64 d
  {
    const float* kb = kI + (size_t)(b * TKDIM + k0) * 64;
#pragma unroll
    for (int l = 0; l < 8; l++) {
      int idx = tid + l * 256;
      int m = idx >> 4, c4 = idx & 15;
      float4 v = *(const float4*)(kb + (size_t)m * 64 + c4 * 4);
      uint2 hi, lo;
      split_f4(v, hi, lo);
      ((uint2*)Bh)[m * 18 + c4] = hi;
      ((uint2*)Bl)[m * 18 + c4] = lo;
    }
  }
  if (tid < 128)
    *(float4*)&ws[tid * 4] =
        *(const float4*)&wI[(size_t)(b * TQDIM + q0 + tid) * 4];

  float acc[2][8][4] = {};
  const float* qb = qI + (size_t)(b * TQDIM + q0) * 256;

  for (int h = 0; h < NHEADS; h++) {
    __syncthreads();  // prev-head readers done before overwrite
#pragma unroll
    for (int l = 0; l < 8; l++) {
      int idx = tid + l * 256;
      int m = idx >> 4, c4 = idx & 15;
      float4 v = *(const float4*)(qb + (size_t)m * 256 + h * 64 + c4 * 4);
      uint2 hi, lo;
      split_f4(v, hi, lo);
      ((uint2*)Ah)[m * 18 + c4] = hi;
      ((uint2*)Al)[m * 18 + c4] = lo;
    }
    __syncthreads();

    float dot[2][8][4] = {};
#pragma unroll
    for (int ks = 0; ks < 4; ks++) {
      uint32_t ah[2][4], al[2][4];
#pragma unroll
      for (int mf = 0; mf < 2; mf++) {
        int r0 = mw + mf * 16 + g, r1 = r0 + 8;
        int w0 = ks * 8 + q4;
        ah[mf][0] = AhW[r0 * SPW + w0];
        ah[mf][1] = AhW[r1 * SPW + w0];
        ah[mf][2] = AhW[r0 * SPW + w0 + 4];
        ah[mf][3] = AhW[r1 * SPW + w0 + 4];
        al[mf][0] = AlW[r0 * SPW + w0];
        al[mf][1] = AlW[r1 * SPW + w0];
        al[mf][2] = AlW[r0 * SPW + w0 + 4];
        al[mf][3] = AlW[r1 * SPW + w0 + 4];
      }
#pragma unroll
      for (int nf = 0; nf < 8; nf++) {
        int n = nw + nf * 8 + g;
        int wb = n * SPW + ks * 8 + q4;
        uint32_t bh0 = BhW[wb], bh1 = BhW[wb + 4];
        uint32_t bl0 = BlW[wb], bl1 = BlW[wb + 4];
#pragma unroll
        for (int mf = 0; mf < 2; mf++) {
          mma_bf16(dot[mf][nf], ah[mf], bh0, bh1);
          mma_bf16(dot[mf][nf], ah[mf], bl0, bl1);
          mma_bf16(dot[mf][nf], al[mf], bh0, bh1);
        }
      }
    }
    // relu + weighted accumulate
#pragma unroll
    for (int mf = 0; mf < 2; mf++) {
      float wa = ws[(mw + mf * 16 + g) * 4 + h];
      float wb2 = ws[(mw + mf * 16 + g + 8) * 4 + h];
#pragma unroll
      for (int nf = 0; nf < 8; nf++) {
        acc[mf][nf][0] = fmaf(wa, fmaxf(dot[mf][nf][0], 0.f), acc[mf][nf][0]);
        acc[mf][nf][1] = fmaf(wa, fmaxf(dot[mf][nf][1], 0.f), acc[mf][nf][1]);
        acc[mf][nf][2] = fmaf(wb2, fmaxf(dot[mf][nf][2], 0.f), acc[mf][nf][2]);
        acc[mf][nf][3] = fmaf(wb2, fmaxf(dot[mf][nf][3], 0.f), acc[mf][nf][3]);
      }
    }
  }

  // store: each 32B sector fully covered (4 lanes x 8B per row segment)
  float* obase = out + (size_t)(b * TQDIM + q0) * TKDIM + k0;
#pragma unroll
  for (int mf = 0; mf < 2; mf++) {
    int r0 = mw + mf * 16 + g;
#pragma unroll
    for (int nf = 0; nf < 8; nf++) {
      int col = nw + nf * 8 + q4 * 2;
      *(float2*)&obase[(size_t)r0 * TKDIM + col] =
          make_float2(acc[mf][nf][0], acc[mf][nf][1]);
      *(float2*)&obase[(size_t)(r0 + 8) * TKDIM + col] =
          make_float2(acc[mf][nf][2], acc[mf][nf][3]);
    }
  }
}

// ---------------------------------------------------------------------------
extern "C" void kernel_launch(void* const* d_in, const int* in_sizes, int n_in,
                              void* d_out, int out_size) {
  const float* x_q = (const float*)d_in[0];
  const float* x_k = (const float*)d_in[1];
  const float* Wq = (const float*)d_in[2];
  const float* Ww = (const float*)d_in[3];
  const float* Wk = (const float*)d_in[4];
  float* out = (float*)d_out;

  float *qI, *kI, *wI;
  cudaGetSymbolAddress((void**)&qI, g_qI);
  cudaGetSymbolAddress((void**)&kI, g_kI);
  cudaGetSymbolAddress((void**)&wI, g_wI);

  const int proj_smem = (128 * SP + 128 * SP + 128 * SP + 128 * SP) * 2;
  cudaFuncSetAttribute(proj_kernel, cudaFuncAttributeMaxDynamicSharedMemorySize,
                       proj_smem);
  cudaFuncSetAttribute(main_mma_kernel,
                       cudaFuncAttributeMaxDynamicSharedMemorySize, MAIN_SMEM);

  proj_kernel<<<192, 256, proj_smem>>>(x_q, x_k, Wq, Wk, qI, kI);
  wproj_kernel<<<2048, 128>>>(x_q, Ww, wI);
  main_mma_kernel<<<dim3(TKDIM / 128, TQDIM / 128, 2), 256, MAIN_SMEM>>>(
      qI, kI, wI, out);
}

// round 4
// speedup vs baseline: 2.0827x; 1.1031x over previous
#include <cuda_runtime.h>
#include <cuda_bf16.h>
#include <cstdint>

// Shapes (fixed)
#define TQDIM 4096
#define TKDIM 4096
#define DMODEL 2048
#define NHEADS 4
#define ROWS 8192  // B*T

#define SP 72   // smem row stride in bf16 halves (conflict-free frag LDS)
#define SPW 36  // stride in 32-bit words

__device__ float g_qI[ROWS * 256];
__device__ float g_kI[ROWS * 64];
__device__ float g_wI[ROWS * 4];

// ---------------------------------------------------------------------------
// helpers
// ---------------------------------------------------------------------------
__device__ __forceinline__ void split1(float v, __nv_bfloat16& h,
                                       __nv_bfloat16& l) {
  h = __float2bfloat16(v);
  l = __float2bfloat16(v - __bfloat162float(h));
}
__device__ __forceinline__ uint32_t pack2(__nv_bfloat16 a, __nv_bfloat16 b) {
  return (uint32_t)__bfloat16_as_ushort(a) |
         ((uint32_t)__bfloat16_as_ushort(b) << 16);
}
__device__ __forceinline__ void split_f4(float4 v, uint2& hi, uint2& lo) {
  __nv_bfloat16 h0, l0, h1, l1, h2, l2, h3, l3;
  split1(v.x, h0, l0); split1(v.y, h1, l1);
  split1(v.z, h2, l2); split1(v.w, h3, l3);
  hi.x = pack2(h0, h1); hi.y = pack2(h2, h3);
  lo.x = pack2(l0, l1); lo.y = pack2(l2, l3);
}

// m16n8k16 row.col f32.bf16.bf16.f32
__device__ __forceinline__ void mma_bf16(float* c, const uint32_t* a,
                                         uint32_t b0, uint32_t b1) {
  asm volatile(
      "mma.sync.aligned.m16n8k16.row.col.f32.bf16.bf16.f32 "
      "{%0,%1,%2,%3}, {%4,%5,%6,%7}, {%8,%9}, {%0,%1,%2,%3};\n"
      : "+f"(c[0]), "+f"(c[1]), "+f"(c[2]), "+f"(c[3])
      : "r"(a[0]), "r"(a[1]), "r"(a[2]), "r"(a[3]), "r"(b0), "r"(b1));
}

// ---------------------------------------------------------------------------
// Projection kernel (bf16x3 via mma.sync), software-pipelined.
//  CTA tile: 128(M) x 64(N), 8 warps, warp tile 16x64 (MF=1).
//  blocks 0..255 : q_I  (M=8192, N=256)   blocks 256..319 : k_I (N=64)
//  2 CTAs/SM: regs <=128, smem 55296.
// ---------------------------------------------------------------------------
#define PROJ_SMEM (128 * SP * 2 * 2 + 64 * SP * 2 * 2)  // 55296 bytes

__global__ __launch_bounds__(256, 2) void proj_kernel(
    const float* __restrict__ xq, const float* __restrict__ xk,
    const float* __restrict__ Wq, const float* __restrict__ Wk,
    float* __restrict__ qI, float* __restrict__ kI) {
  extern __shared__ __align__(16) char smem[];
  __nv_bfloat16* Ah = (__nv_bfloat16*)smem;   // 128*SP
  __nv_bfloat16* Al = Ah + 128 * SP;
  __nv_bfloat16* Bh = Al + 128 * SP;          // 64*SP
  __nv_bfloat16* Bl = Bh + 64 * SP;
  const uint32_t* AhW = (const uint32_t*)Ah;
  const uint32_t* AlW = (const uint32_t*)Al;
  const uint32_t* BhW = (const uint32_t*)Bh;
  const uint32_t* BlW = (const uint32_t*)Bl;

  const int bx = blockIdx.x;
  const bool isQ = bx < 256;
  const int Nld = isQ ? 256 : 64;
  const int m0 = isQ ? (bx >> 2) * 128 : (bx - 256) * 128;
  const int n0 = isQ ? (bx & 3) * 64 : 0;
  const float* A = isQ ? xq : xk;
  const float* W = isQ ? Wq : Wk;
  float* C = isQ ? qI : kI;

  const int tid = threadIdx.x;
  const int wid = tid >> 5, lane = tid & 31;
  const int g = lane >> 2, q4 = lane & 3;
  const int mw = wid * 16;

  // per-thread load coords
  const int am = tid >> 4;              // A: row, 2 rows covered per l-step? no:
  const int ac4 = tid & 15;             // A: float4 index within 64-col row
  const int wn = tid & 63;              // W: column within tile
  const int wk0 = tid >> 6;             // W: base kk (0..3), stride 4

  float4 RA[8];
  float RW[16];

  // ---- load chunk kc into registers ----
  auto ldg_chunk = [&](int kc) {
#pragma unroll
    for (int l = 0; l < 8; l++) {
      int m = am + l * 16;
      RA[l] = *(const float4*)(A + (size_t)(m0 + m) * DMODEL + kc * 64 +
                               ac4 * 4);
    }
#pragma unroll
    for (int j = 0; j < 16; j++) {
      int kk = wk0 + j * 4;
      RW[j] = W[(size_t)(kc * 64 + kk) * Nld + n0 + wn];
    }
  };
  // ---- store registers into smem (with hi/lo split) ----
  auto st_chunk = [&]() {
#pragma unroll
    for (int l = 0; l < 8; l++) {
      int m = am + l * 16;
      uint2 hi, lo;
      split_f4(RA[l], hi, lo);
      ((uint2*)Ah)[m * 18 + ac4] = hi;
      ((uint2*)Al)[m * 18 + ac4] = lo;
    }
#pragma unroll
    for (int j = 0; j < 16; j++) {
      int kk = wk0 + j * 4;
      __nv_bfloat16 h, l;
      split1(RW[j], h, l);
      Bh[wn * SP + kk] = h;
      Bl[wn * SP + kk] = l;
    }
  };

  float dot[8][4] = {};

  ldg_chunk(0);
  st_chunk();
  __syncthreads();

  for (int kc = 0; kc < DMODEL / 64; kc++) {
    if (kc + 1 < DMODEL / 64) ldg_chunk(kc + 1);  // overlap with MMA below

#pragma unroll
    for (int ks = 0; ks < 4; ks++) {
      uint32_t ah[4], al[4];
      const int r0 = mw + g, w0 = ks * 8 + q4;
      ah[0] = AhW[r0 * SPW + w0];
      ah[1] = AhW[(r0 + 8) * SPW + w0];
      ah[2] = AhW[r0 * SPW + w0 + 4];
      ah[3] = AhW[(r0 + 8) * SPW + w0 + 4];
      al[0] = AlW[r0 * SPW + w0];
      al[1] = AlW[(r0 + 8) * SPW + w0];
      al[2] = AlW[r0 * SPW + w0 + 4];
      al[3] = AlW[(r0 + 8) * SPW + w0 + 4];
#pragma unroll
      for (int nf = 0; nf < 8; nf++) {
        int wb = (nf * 8 + g) * SPW + ks * 8 + q4;
        uint32_t bh0 = BhW[wb], bh1 = BhW[wb + 4];
        uint32_t bl0 = BlW[wb], bl1 = BlW[wb + 4];
        mma_bf16(dot[nf], ah, bh0, bh1);
        mma_bf16(dot[nf], ah, bl0, bl1);
        mma_bf16(dot[nf], al, bh0, bh1);
      }
    }
    if (kc + 1 < DMODEL / 64) {
      __syncthreads();  // all warps done reading smem
      st_chunk();
      __syncthreads();  // smem ready for next iter
    }
  }

  // epilogue
  const int r0 = m0 + mw + g;
#pragma unroll
  for (int nf = 0; nf < 8; nf++) {
    int col = n0 + nf * 8 + q4 * 2;
    *(float2*)&C[(size_t)r0 * Nld + col] = make_float2(dot[nf][0], dot[nf][1]);
    *(float2*)&C[(size_t)(r0 + 8) * Nld + col] =
        make_float2(dot[nf][2], dot[nf][3]);
  }
}

// ---------------------------------------------------------------------------
// w_I = x_q @ Ww (N=4): one warp per row.
// ---------------------------------------------------------------------------
__global__ __launch_bounds__(128) void wproj_kernel(
    const float* __restrict__ x, const float* __restrict__ Ww,
    float* __restrict__ wI) {
  int row = blockIdx.x * 4 + (threadIdx.x >> 5);
  int lane = threadIdx.x & 31;
  const float* xr = x + (size_t)row * DMODEL;
  float a0 = 0.f, a1 = 0.f, a2 = 0.f, a3 = 0.f;
  for (int d = lane; d < DMODEL; d += 32) {
    float xv = xr[d];
    float4 w = *(const float4*)&Ww[d * 4];
    a0 = fmaf(xv, w.x, a0);
    a1 = fmaf(xv, w.y, a1);
    a2 = fmaf(xv, w.z, a2);
    a3 = fmaf(xv, w.w, a3);
  }
#pragma unroll
  for (int off = 16; off; off >>= 1) {
    a0 += __shfl_down_sync(0xffffffffu, a0, off);
    a1 += __shfl_down_sync(0xffffffffu, a1, off);
    a2 += __shfl_down_sync(0xffffffffu, a2, off);
    a3 += __shfl_down_sync(0xffffffffu, a3, off);
  }
  if (lane == 0) *(float4*)&wI[(size_t)row * 4] = make_float4(a0, a1, a2, a3);
}

// ---------------------------------------------------------------------------
// Main kernel: 128q x 128k tile, 8 warps (4x2), warp tile 32x64.
// Per head: dot (bf16x3 HMMA) -> relu -> w-weighted accumulate.
// Next head's q chunk is register-prefetched during the current head's MMAs.
// ---------------------------------------------------------------------------
#define MAIN_SMEM (128 * SP * 2 * 2 * 2 + 128 * 4 * 4)  // 75776

__global__ __launch_bounds__(256, 1) void main_mma_kernel(
    const float* __restrict__ qI, const float* __restrict__ kI,
    const float* __restrict__ wI, float* __restrict__ out) {
  extern __shared__ __align__(16) char smem[];
  __nv_bfloat16* Ah = (__nv_bfloat16*)smem;   // q tile hi (per head)
  __nv_bfloat16* Al = Ah + 128 * SP;
  __nv_bfloat16* Bh = Al + 128 * SP;          // k tile hi
  __nv_bfloat16* Bl = Bh + 128 * SP;
  float* ws = (float*)(Bl + 128 * SP);        // 128 x 4
  const uint32_t* AhW = (const uint32_t*)Ah;
  const uint32_t* AlW = (const uint32_t*)Al;
  const uint32_t* BhW = (const uint32_t*)Bh;
  const uint32_t* BlW = (const uint32_t*)Bl;

  const int tid = threadIdx.x;
  const int wid = tid >> 5, lane = tid & 31;
  const int g = lane >> 2, q4 = lane & 3;
  const int mw = (wid >> 1) * 32, nw = (wid & 1) * 64;
  const int b = blockIdx.z, q0 = blockIdx.y * 128, k0 = blockIdx.x * 128;

  const int am = tid >> 4;   // row within tile (x16 per l)
  const int ac4 = tid & 15;  // float4 index within 64-col row

  const float* qb = qI + (size_t)(b * TQDIM + q0) * 256;
  float4 Rq[8];

  auto ldg_q = [&](int h) {
#pragma unroll
    for (int l = 0; l < 8; l++) {
      int m = am + l * 16;
      Rq[l] = *(const float4*)(qb + (size_t)m * 256 + h * 64 + ac4 * 4);
    }
  };
  auto st_q = [&]() {
#pragma unroll
    for (int l = 0; l < 8; l++) {
      int m = am + l * 16;
      uint2 hi, lo;
      split_f4(Rq[l], hi, lo);
      ((uint2*)Ah)[m * 18 + ac4] = hi;
      ((uint2*)Al)[m * 18 + ac4] = lo;
    }
  };

  // prologue: k tile (shared across heads) + ws + q head 0
  {
    const float* kb = kI + (size_t)(b * TKDIM + k0) * 64;
#pragma unroll
    for (int l = 0; l < 8; l++) {
      int m = am + l * 16;
      float4 v = *(const float4*)(kb + (size_t)m * 64 + ac4 * 4);
      uint2 hi, lo;
      split_f4(v, hi, lo);
      ((uint2*)Bh)[m * 18 + ac4] = hi;
      ((uint2*)Bl)[m * 18 + ac4] = lo;
    }
  }
  if (tid < 128)
    *(float4*)&ws[tid * 4] =
        *(const float4*)&wI[(size_t)(b * TQDIM + q0 + tid) * 4];
  ldg_q(0);
  st_q();
  __syncthreads();

  float acc[2][8][4] = {};

  for (int h = 0; h < NHEADS; h++) {
    if (h + 1 < NHEADS) ldg_q(h + 1);  // overlap with MMAs

    float dot[2][8][4] = {};
#pragma unroll
    for (int ks = 0; ks < 4; ks++) {
      uint32_t ah[2][4], al[2][4];
#pragma unroll
      for (int mf = 0; mf < 2; mf++) {
        int r0 = mw + mf * 16 + g, r1 = r0 + 8;
        int w0 = ks * 8 + q4;
        ah[mf][0] = AhW[r0 * SPW + w0];
        ah[mf][1] = AhW[r1 * SPW + w0];
        ah[mf][2] = AhW[r0 * SPW + w0 + 4];
        ah[mf][3] = AhW[r1 * SPW + w0 + 4];
        al[mf][0] = AlW[r0 * SPW + w0];
        al[mf][1] = AlW[r1 * SPW + w0];
        al[mf][2] = AlW[r0 * SPW + w0 + 4];
        al[mf][3] = AlW[r1 * SPW + w0 + 4];
      }
#pragma unroll
      for (int nf = 0; nf < 8; nf++) {
        int wb = (nw + nf * 8 + g) * SPW + ks * 8 + q4;
        uint32_t bh0 = BhW[wb], bh1 = BhW[wb + 4];
        uint32_t bl0 = BlW[wb], bl1 = BlW[wb + 4];
#pragma unroll
        for (int mf = 0; mf < 2; mf++) {
          mma_bf16(dot[mf][nf], ah[mf], bh0, bh1);
          mma_bf16(dot[mf][nf], ah[mf], bl0, bl1);
          mma_bf16(dot[mf][nf], al[mf], bh0, bh1);
        }
      }
    }
    // relu + weighted accumulate
#pragma unroll
    for (int mf = 0; mf < 2; mf++) {
      float wa = ws[(mw + mf * 16 + g) * 4 + h];
      float wb2 = ws[(mw + mf * 16 + g + 8) * 4 + h];
#pragma unroll
      for (int nf = 0; nf < 8; nf++) {
        acc[mf][nf][0] = fmaf(wa, fmaxf(dot[mf][nf][0], 0.f), acc[mf][nf][0]);
        acc[mf][nf][1] = fmaf(wa, fmaxf(dot[mf][nf][1], 0.f), acc[mf][nf][1]);
        acc[mf][nf][2] = fmaf(wb2, fmaxf(dot[mf][nf][2], 0.f), acc[mf][nf][2]);
        acc[mf][nf][3] = fmaf(wb2, fmaxf(dot[mf][nf][3], 0.f), acc[mf][nf][3]);
      }
    }
    if (h + 1 < NHEADS) {
      __syncthreads();
      st_q();
      __syncthreads();
    }
  }

  float* obase = out + (size_t)(b * TQDIM + q0) * TKDIM + k0;
#pragma unroll
  for (int mf = 0; mf < 2; mf++) {
    int r0 = mw + mf * 16 + g;
#pragma unroll
    for (int nf = 0; nf < 8; nf++) {
      int col = nw + nf * 8 + q4 * 2;
      *(float2*)&obase[(size_t)r0 * TKDIM + col] =
          make_float2(acc[mf][nf][0], acc[mf][nf][1]);
      *(float2*)&obase[(size_t)(r0 + 8) * TKDIM + col] =
          make_float2(acc[mf][nf][2], acc[mf][nf][3]);
    }
  }
}

// ---------------------------------------------------------------------------
extern "C" void kernel_launch(void* const* d_in, const int* in_sizes, int n_in,
                              void* d_out, int out_size) {
  const float* x_q = (const float*)d_in[0];
  const float* x_k = (const float*)d_in[1];
  const float* Wq = (const float*)d_in[2];
  const float* Ww = (const float*)d_in[3];
  const float* Wk = (const float*)d_in[4];
  float* out = (float*)d_out;

  float *qI, *kI, *wI;
  cudaGetSymbolAddress((void**)&qI, g_qI);
  cudaGetSymbolAddress((void**)&kI, g_kI);
  cudaGetSymbolAddress((void**)&wI, g_wI);

  cudaFuncSetAttribute(proj_kernel, cudaFuncAttributeMaxDynamicSharedMemorySize,
                       PROJ_SMEM);
  cudaFuncSetAttribute(main_mma_kernel,
                       cudaFuncAttributeMaxDynamicSharedMemorySize, MAIN_SMEM);

  proj_kernel<<<320, 256, PROJ_SMEM>>>(x_q, x_k, Wq, Wk, qI, kI);
  wproj_kernel<<<2048, 128>>>(x_q, Ww, wI);
  main_mma_kernel<<<dim3(TKDIM / 128, TQDIM / 128, 2), 256, MAIN_SMEM>>>(
      qI, kI, wI, out);
}